// round 6
// baseline (speedup 1.0000x reference)
#include <cuda_runtime.h>
#include <stdint.h>

// AddRadiusEdgeIndex: dense [N,N] float32 mask (1.0f/0.0f),
// mask[i,j] = (||p_i - p_j|| <= 3), reference-exact fp32 rounding:
//   sq  = (x*x + y*y) + z*z                         (plain rn mul/add)
//   dot = fmaf(z_i,z_j, fmaf(y_i,y_j, x_i*x_j))     (gemm k-loop fma chain)
//   d2  = rn((sq_i + sq_j) - 2*dot)                 (fmaf(-2,dot,s): 2*dot exact)
//   mask = d2 <= 9                                  (clamp irrelevant, 9>0)
//
// R5 -> R6: R3/R4/R5 all pinned at ~40.8us with NOTHING saturated (DRAM 65%,
// L1 67%, issue 38%) -> the invariant is the per-warp STG/L1tex store path.
// This round removes it: compute into SMEM (STS), drain with TMA bulk stores
// (cp.async.bulk.global.shared::cta), double-buffered 4-row groups.

#define NPTS 8192
#define JPT  4      // j-points per thread
#define TPB  256    // 1024 j-cols per block
#define IPB  16     // i-rows per block; grid = 8 * 512 = 4096
#define ROWS_PER_GRP 4
#define NGRP (IPB / ROWS_PER_GRP)
#define ROWF 1024                    // floats per block-row
#define ROW_BYTES (ROWF * 4)         // 4 KB per bulk store

__device__ __forceinline__ float set_le(float a, float b)
{
    float r;
    asm("set.le.f32.f32 %0, %1, %2;" : "=f"(r) : "f"(a), "f"(b));
    return r;  // (a <= b) ? 1.0f : 0.0f
}

__device__ __forceinline__ uint32_t smem_u32(const void* p)
{
    uint32_t a;
    asm("{ .reg .u64 t; cvta.to.shared.u64 t, %1; cvt.u32.u64 %0, t; }"
        : "=r"(a) : "l"(p));
    return a;
}

__global__ __launch_bounds__(TPB, 6)
void radius_mask_kernel(const float* __restrict__ pos, float* __restrict__ out)
{
    __shared__ float4 si[IPB];                       // (x, y, z, sq) i-rows
    __shared__ float  buf[2][ROWS_PER_GRP][ROWF];    // ping-pong output tiles

    const int t  = threadIdx.x;
    const int jb = blockIdx.x & 7;          // j-block: 8 per row-stripe
    const int ib = blockIdx.x >> 3;         // i-stripe: 512 of them
    const int i0 = ib * IPB;
    const int j0 = jb * (TPB * JPT) + t * JPT;

    if (t < IPB) {
        const int i = i0 + t;
        float x = pos[3 * i + 0];
        float y = pos[3 * i + 1];
        float z = pos[3 * i + 2];
        float sq = __fadd_rn(__fadd_rn(__fmul_rn(x, x), __fmul_rn(y, y)),
                             __fmul_rn(z, z));
        si[t] = make_float4(x, y, z, sq);
    }

    // 4 register-resident j-points
    float xj[JPT], yj[JPT], zj[JPT], sj[JPT];
#pragma unroll
    for (int k = 0; k < JPT; k++) {
        const int j = j0 + k;
        float x = pos[3 * j + 0];
        float y = pos[3 * j + 1];
        float z = pos[3 * j + 2];
        xj[k] = x; yj[k] = y; zj[k] = z;
        sj[k] = __fadd_rn(__fadd_rn(__fmul_rn(x, x), __fmul_rn(y, y)),
                          __fmul_rn(z, z));
    }

    __syncthreads();   // si ready

    // gmem base for this block's 1024-col stripe
    float* gbase = out + (size_t)i0 * NPTS + (size_t)jb * ROWF;

#pragma unroll
    for (int g = 0; g < NGRP; g++) {
        const int b = g & 1;

        // buffer b free? (group g-2's TMA reads must be done)
        if (g >= 2) {
            if (t == 0)
                asm volatile("cp.async.bulk.wait_group.read 1;" ::: "memory");
            __syncthreads();
        }

        // compute 4 rows into buf[b]
#pragma unroll
        for (int r = 0; r < ROWS_PER_GRP; r++) {
            const float4 p = si[g * ROWS_PER_GRP + r];   // broadcast LDS.128
            float v[JPT];
#pragma unroll
            for (int m = 0; m < JPT; m++) {
                float dot = __fmaf_rn(zj[m], p.z,
                             __fmaf_rn(yj[m], p.y, __fmul_rn(xj[m], p.x)));
                float d2  = __fmaf_rn(-2.0f, dot, __fadd_rn(p.w, sj[m]));
                v[m] = set_le(d2, 9.0f);
            }
            ((float4*)buf[b][r])[t] = make_float4(v[0], v[1], v[2], v[3]);
        }

        __syncthreads();   // STS visible block-wide

        if (t == 0) {
            asm volatile("fence.proxy.async.shared::cta;" ::: "memory");
#pragma unroll
            for (int r = 0; r < ROWS_PER_GRP; r++) {
                uint32_t src = smem_u32(&buf[b][r][0]);
                float* dst = gbase + (size_t)(g * ROWS_PER_GRP + r) * NPTS;
                asm volatile(
                    "cp.async.bulk.global.shared::cta.bulk_group [%0], [%1], %2;"
                    :: "l"(dst), "r"(src), "r"(ROW_BYTES) : "memory");
            }
            asm volatile("cp.async.bulk.commit_group;" ::: "memory");
        }
    }

    // drain all bulk stores before kernel exit
    if (t == 0)
        asm volatile("cp.async.bulk.wait_group 0;" ::: "memory");
}

extern "C" void kernel_launch(void* const* d_in, const int* in_sizes, int n_in,
                              void* d_out, int out_size)
{
    const float* pos = (const float*)d_in[0];
    float* out = (float*)d_out;
    radius_mask_kernel<<<(NPTS / (TPB * JPT)) * (NPTS / IPB), TPB>>>(pos, out);
}

// round 7
// speedup vs baseline: 1.4938x; 1.4938x over previous
#include <cuda_runtime.h>
#include <stdint.h>

// AddRadiusEdgeIndex: dense [N,N] float32 mask (1.0f/0.0f),
// mask[i,j] = (||p_i - p_j|| <= 3), reference-exact fp32 rounding:
//   sq  = (x*x + y*y) + z*z                       (plain rn mul/add)
//   dot = fmaf(z,z', fmaf(y,y', x*x'))            (gemm k-loop fma chain)
//   d2  = fmaf(-2, dot, sq_i + sq_j)              (2*dot exact)
//   mask = d2 <= 9
//
// R6 -> R7: revert to R5 structure (TMA drain regressed; pipeline serialized).
// New lever: packed f32x2 math (FFMA2/FADD2/FMUL2, PTX-only on sm_103a).
// 6 FMA-pipe ops/elem -> 2.5, per-lane .rn bit-identical to scalar chain.
// i-tile staged in smem PRE-PACKED as broadcast pairs {x,x}{y,y}{z,z}{q,q}
// so the inner loop does zero packing: 2x LDS.128 per i-row.

#define NPTS 8192
#define JPT  4     // j-points per thread (= 2 packed lanes)
#define TPB  256   // 1024 j-cols per block
#define IPB  16    // i-rows per block; grid = 8 * 512 = 4096

typedef unsigned long long u64;

__device__ __forceinline__ u64 pack2(float lo, float hi)
{
    u64 r; asm("mov.b64 %0, {%1, %2};" : "=l"(r) : "f"(lo), "f"(hi)); return r;
}
__device__ __forceinline__ u64 mul2(u64 a, u64 b)
{
    u64 r; asm("mul.rn.f32x2 %0, %1, %2;" : "=l"(r) : "l"(a), "l"(b)); return r;
}
__device__ __forceinline__ u64 add2(u64 a, u64 b)
{
    u64 r; asm("add.rn.f32x2 %0, %1, %2;" : "=l"(r) : "l"(a), "l"(b)); return r;
}
__device__ __forceinline__ u64 fma2(u64 a, u64 b, u64 c)
{
    u64 r; asm("fma.rn.f32x2 %0, %1, %2, %3;" : "=l"(r) : "l"(a), "l"(b), "l"(c)); return r;
}
__device__ __forceinline__ float set_le9(float a)
{
    float r; asm("set.le.f32.f32 %0, %1, 0f41100000;" : "=f"(r) : "f"(a)); return r;
}

__global__ __launch_bounds__(TPB, 6)
void radius_mask_kernel(const float* __restrict__ pos, float4* __restrict__ out)
{
    // per i-row, pre-packed broadcasts: [0]={x,x | y,y}  [1]={z,z | q,q}
    __shared__ ulonglong2 si2[IPB][2];

    const int t  = threadIdx.x;
    const int jb = blockIdx.x & 7;          // j-block: 8 per row-stripe
    const int ib = blockIdx.x >> 3;         // i-stripe: 512 of them
    const int i0 = ib * IPB;
    const int j0 = jb * (TPB * JPT) + t * JPT;

    if (t < IPB) {
        const int i = i0 + t;
        float x = pos[3 * i + 0];
        float y = pos[3 * i + 1];
        float z = pos[3 * i + 2];
        float q = __fadd_rn(__fadd_rn(__fmul_rn(x, x), __fmul_rn(y, y)),
                            __fmul_rn(z, z));
        si2[t][0] = make_ulonglong2(pack2(x, x), pack2(y, y));
        si2[t][1] = make_ulonglong2(pack2(z, z), pack2(q, q));
    }

    // 4 register-resident j-points as 2 packed lanes
    u64 xj2[2], yj2[2], zj2[2], sj2[2];
#pragma unroll
    for (int g = 0; g < 2; g++) {
        float xa = pos[3 * (j0 + 2 * g) + 0];
        float ya = pos[3 * (j0 + 2 * g) + 1];
        float za = pos[3 * (j0 + 2 * g) + 2];
        float xb = pos[3 * (j0 + 2 * g + 1) + 0];
        float yb = pos[3 * (j0 + 2 * g + 1) + 1];
        float zb = pos[3 * (j0 + 2 * g + 1) + 2];
        float qa = __fadd_rn(__fadd_rn(__fmul_rn(xa, xa), __fmul_rn(ya, ya)),
                             __fmul_rn(za, za));
        float qb = __fadd_rn(__fadd_rn(__fmul_rn(xb, xb), __fmul_rn(yb, yb)),
                             __fmul_rn(zb, zb));
        xj2[g] = pack2(xa, xb);
        yj2[g] = pack2(ya, yb);
        zj2[g] = pack2(za, zb);
        sj2[g] = pack2(qa, qb);
    }

    __syncthreads();

    const u64 NEG2 = 0xC0000000C0000000ull;   // {-2.0f, -2.0f}

    float4* dst = out + (size_t)i0 * (NPTS / 4) + (j0 >> 2);

#pragma unroll 8
    for (int ii = 0; ii < IPB; ii++) {
        const ulonglong2 A = si2[ii][0];      // {xx, yy}  LDS.128 broadcast
        const ulonglong2 B = si2[ii][1];      // {zz, qq}

        float v[JPT];
#pragma unroll
        for (int g = 0; g < 2; g++) {
            u64 dot = fma2(zj2[g], B.x, fma2(yj2[g], A.y, mul2(xj2[g], A.x)));
            u64 d2  = fma2(NEG2, dot, add2(B.y, sj2[g]));
            float lo, hi;
            asm("mov.b64 {%0, %1}, %2;" : "=f"(lo), "=f"(hi) : "l"(d2));
            v[2 * g + 0] = set_le9(lo);
            v[2 * g + 1] = set_le9(hi);
        }
        *dst = make_float4(v[0], v[1], v[2], v[3]);
        dst += NPTS / 4;
    }
}

extern "C" void kernel_launch(void* const* d_in, const int* in_sizes, int n_in,
                              void* d_out, int out_size)
{
    const float* pos = (const float*)d_in[0];
    float4* out = (float4*)d_out;
    radius_mask_kernel<<<(NPTS / (TPB * JPT)) * (NPTS / IPB), TPB>>>(pos, out);
}

// round 8
// speedup vs baseline: 1.4950x; 1.0008x over previous
#include <cuda_runtime.h>
#include <stdint.h>

// AddRadiusEdgeIndex: dense [N,N] float32 mask (1.0f/0.0f),
// mask[i,j] = (||p_i - p_j|| <= 3), reference-exact fp32 rounding (rel_err==0):
//   sq  = (x*x + y*y) + z*z ; dot = fmaf-chain ; d2 = fmaf(-2,dot,sq_i+sq_j)
//   mask = d2 <= 9
//
// R7 -> R8: four kernels pinned at ~40.5us => ~5.15 TB/s is the HBM pure-write
// ceiling; only 209 of 268 MB/iter reach DRAM (59 MB stay dirty in L2 across
// graph replays). Lever: pin rows [0,3072) (96 MB) with L2::evict_last cache
// hints so they are rewritten in place in L2 forever; stream the rest with
// evict_first. Steady-state DRAM traffic 209 -> ~160 MB/iter.

#define NPTS 8192
#define JPT  4
#define TPB  256
#define IPB  16
#define PIN_ROWS 3072   // 3072 * 32 KB = 96 MB pinned window (< 126 MB L2)

typedef unsigned long long u64;

__device__ __forceinline__ u64 pack2(float lo, float hi)
{
    u64 r; asm("mov.b64 %0, {%1, %2};" : "=l"(r) : "f"(lo), "f"(hi)); return r;
}
__device__ __forceinline__ u64 mul2(u64 a, u64 b)
{
    u64 r; asm("mul.rn.f32x2 %0, %1, %2;" : "=l"(r) : "l"(a), "l"(b)); return r;
}
__device__ __forceinline__ u64 add2(u64 a, u64 b)
{
    u64 r; asm("add.rn.f32x2 %0, %1, %2;" : "=l"(r) : "l"(a), "l"(b)); return r;
}
__device__ __forceinline__ u64 fma2(u64 a, u64 b, u64 c)
{
    u64 r; asm("fma.rn.f32x2 %0, %1, %2, %3;" : "=l"(r) : "l"(a), "l"(b), "l"(c)); return r;
}
__device__ __forceinline__ float set_le9(float a)
{
    float r; asm("set.le.f32.f32 %0, %1, 0f41100000;" : "=f"(r) : "f"(a)); return r;
}
__device__ __forceinline__ void stg_hint_v4(float4* p, float a, float b,
                                            float c, float d, u64 pol)
{
    asm volatile("st.global.L2::cache_hint.v4.f32 [%0], {%1, %2, %3, %4}, %5;"
                 :: "l"(p), "f"(a), "f"(b), "f"(c), "f"(d), "l"(pol) : "memory");
}

__global__ __launch_bounds__(TPB, 6)
void radius_mask_kernel(const float* __restrict__ pos, float4* __restrict__ out)
{
    __shared__ ulonglong2 si2[IPB][2];   // per i-row: {x,x|y,y}, {z,z|q,q}

    const int t  = threadIdx.x;
    const int jb = blockIdx.x & 7;
    const int ib = blockIdx.x >> 3;
    const int i0 = ib * IPB;
    const int j0 = jb * (TPB * JPT) + t * JPT;

    if (t < IPB) {
        const int i = i0 + t;
        float x = pos[3 * i + 0];
        float y = pos[3 * i + 1];
        float z = pos[3 * i + 2];
        float q = __fadd_rn(__fadd_rn(__fmul_rn(x, x), __fmul_rn(y, y)),
                            __fmul_rn(z, z));
        si2[t][0] = make_ulonglong2(pack2(x, x), pack2(y, y));
        si2[t][1] = make_ulonglong2(pack2(z, z), pack2(q, q));
    }

    // 4 register-resident j-points as 2 packed lanes
    u64 xj2[2], yj2[2], zj2[2], sj2[2];
#pragma unroll
    for (int g = 0; g < 2; g++) {
        float xa = pos[3 * (j0 + 2 * g) + 0];
        float ya = pos[3 * (j0 + 2 * g) + 1];
        float za = pos[3 * (j0 + 2 * g) + 2];
        float xb = pos[3 * (j0 + 2 * g + 1) + 0];
        float yb = pos[3 * (j0 + 2 * g + 1) + 1];
        float zb = pos[3 * (j0 + 2 * g + 1) + 2];
        float qa = __fadd_rn(__fadd_rn(__fmul_rn(xa, xa), __fmul_rn(ya, ya)),
                             __fmul_rn(za, za));
        float qb = __fadd_rn(__fadd_rn(__fmul_rn(xb, xb), __fmul_rn(yb, yb)),
                             __fmul_rn(zb, zb));
        xj2[g] = pack2(xa, xb);
        yj2[g] = pack2(ya, yb);
        zj2[g] = pack2(za, zb);
        sj2[g] = pack2(qa, qb);
    }

    __syncthreads();

    // L2 eviction policies: pinned window rewrites in place, rest streams.
    u64 pol_last, pol_first;
    asm("createpolicy.fractional.L2::evict_last.b64 %0, 1.0;"  : "=l"(pol_last));
    asm("createpolicy.fractional.L2::evict_first.b64 %0, 1.0;" : "=l"(pol_first));
    const u64 pol = (i0 < PIN_ROWS) ? pol_last : pol_first;  // uniform per block

    const u64 NEG2 = 0xC0000000C0000000ull;   // {-2.0f, -2.0f}

    float4* dst = out + (size_t)i0 * (NPTS / 4) + (j0 >> 2);

#pragma unroll 8
    for (int ii = 0; ii < IPB; ii++) {
        const ulonglong2 A = si2[ii][0];      // LDS.128 broadcast
        const ulonglong2 B = si2[ii][1];

        float v[JPT];
#pragma unroll
        for (int g = 0; g < 2; g++) {
            u64 dot = fma2(zj2[g], B.x, fma2(yj2[g], A.y, mul2(xj2[g], A.x)));
            u64 d2  = fma2(NEG2, dot, add2(B.y, sj2[g]));
            float lo, hi;
            asm("mov.b64 {%0, %1}, %2;" : "=f"(lo), "=f"(hi) : "l"(d2));
            v[2 * g + 0] = set_le9(lo);
            v[2 * g + 1] = set_le9(hi);
        }
        stg_hint_v4(dst, v[0], v[1], v[2], v[3], pol);
        dst += NPTS / 4;
    }
}

extern "C" void kernel_launch(void* const* d_in, const int* in_sizes, int n_in,
                              void* d_out, int out_size)
{
    const float* pos = (const float*)d_in[0];
    float4* out = (float4*)d_out;
    radius_mask_kernel<<<(NPTS / (TPB * JPT)) * (NPTS / IPB), TPB>>>(pos, out);
}